// round 16
// baseline (speedup 1.0000x reference)
#include <cuda_runtime.h>
#include <cuda_bf16.h>
#include <cstdint>

// LinearKAN via warp-level bf16 mma.sync (m16n8k16) with hi/lo compensation.
//   out[b,o] = sum_{j,i} basis_j(x[b,i]) * W2[(j,i),o]
//   basis_0 = silu(x), basis_j = T_j(clip(tanh(x)));  W2[(j,i),o] = j==0 ? w[i,o] : c[i,o,j-1]*w[i,o]
// Grid (8 o-tiles x 32 i-splits) x 256 threads (8 warps), 80KB smem -> 2 CTAs/SM:
// co-resident CTAs overlap build-phase DRAM latency with MMA work.
// A,B stored as bf16 hi+lo; D = Ah*Bh + Ah*Bl + Al*Bh in f32 accum (drop lo*lo).

#define BATCH 64
#define INF   512
#define OUTF  512
#define BASIS 8

#define NSPLIT 32
#define ISPL   (INF / NSPLIT)      // 16 i's per CTA
#define NO     64                  // o's per CTA
#define NCOL   (OUTF / NO)         // 8
#define KB     (9 * ISPL)          // 144 k per CTA
#define NK16   (KB / 16)           // 9 k16 steps per pass

// smem pitches (bytes): 16B-aligned; row offsets mod 128 cycle 8 distinct segments
#define APIT 304                   // A row pitch (288B data + 16 pad)
#define BPIT 144                   // B row pitch (128B data + 16 pad)

#define SM_AHI 0
#define SM_ALO (SM_AHI + 64 * APIT)        // 19456
#define SM_BHI (SM_ALO + 64 * APIT)        // 38912
#define SM_BLO (SM_BHI + KB * BPIT)        // 59648
#define SM_TOT (SM_BLO + KB * BPIT)        // 80384

__device__ float g_partial[NSPLIT * BATCH * OUTF];   // 4 MB
__device__ int   g_ctr[NCOL];                        // zero-init; self-resetting

// ---------------- helpers ----------------
__device__ __forceinline__ uint32_t smem_u32(const void* p) {
    uint32_t a;
    asm("{ .reg .u64 t; cvta.to.shared.u64 t, %1; cvt.u32.u64 %0, t; }" : "=r"(a) : "l"(p));
    return a;
}
__device__ __forceinline__ void hilo2(float v0, float v1, uint32_t& hi, uint32_t& lo) {
    asm("cvt.rn.bf16x2.f32 %0, %1, %2;" : "=r"(hi) : "f"(v1), "f"(v0));  // low16 = v0
    float h0 = __uint_as_float(hi << 16);
    float h1 = __uint_as_float(hi & 0xffff0000u);
    float l0 = v0 - h0, l1 = v1 - h1;
    asm("cvt.rn.bf16x2.f32 %0, %1, %2;" : "=r"(lo) : "f"(l1), "f"(l0));
}
__device__ __forceinline__ void ldmA(uint32_t* a, uint32_t addr) {
    asm volatile("ldmatrix.sync.aligned.m8n8.x4.shared.b16 {%0,%1,%2,%3}, [%4];"
                 : "=r"(a[0]), "=r"(a[1]), "=r"(a[2]), "=r"(a[3]) : "r"(addr));
}
__device__ __forceinline__ void ldmB(uint32_t* b, uint32_t addr) {
    asm volatile("ldmatrix.sync.aligned.m8n8.x2.trans.shared.b16 {%0,%1}, [%2];"
                 : "=r"(b[0]), "=r"(b[1]) : "r"(addr));
}
__device__ __forceinline__ void mma16816(float* d, const uint32_t* a, const uint32_t* b) {
    asm volatile("mma.sync.aligned.m16n8k16.row.col.f32.bf16.bf16.f32 "
                 "{%0,%1,%2,%3}, {%4,%5,%6,%7}, {%8,%9}, {%0,%1,%2,%3};"
                 : "+f"(d[0]), "+f"(d[1]), "+f"(d[2]), "+f"(d[3])
                 : "r"(a[0]), "r"(a[1]), "r"(a[2]), "r"(a[3]), "r"(b[0]), "r"(b[1]));
}

__global__ __launch_bounds__(256, 2)
void kan_mma(const float* __restrict__ x,
             const float* __restrict__ w,
             const float* __restrict__ c,
             float* __restrict__ out) {
    extern __shared__ char sm[];
    __shared__ int s_last;

    const int tid  = threadIdx.x;
    const int wid  = tid >> 5, lane = tid & 31;
    const int o0   = blockIdx.x * NO;
    const int ks   = blockIdx.y;
    const int i0   = ks * ISPL;

    // ================= build A: basis hi/lo, [b][k] rows, k = j*16 + i =================
    // 256 tasks (b, i-quad) -> exactly 1 rep
    {
        const int b  = tid >> 2;
        const int iq = (tid & 3) * 4;
        float4 xv = *reinterpret_cast<const float4*>(&x[(size_t)b * INF + i0 + iq]);
        float v[4] = {xv.x, xv.y, xv.z, xv.w};
        float sil[4], t[4], tm1[4], tm2[4];
#pragma unroll
        for (int u = 0; u < 4; u++) {
            sil[u] = v[u] / (1.0f + __expf(-v[u]));
            float tt = tanhf(v[u]);
            t[u] = fminf(fmaxf(tt, -1.0f + 1e-6f), 1.0f - 1e-6f);
        }
        const int rowoff = b * APIT + iq * 2;
        auto stA = [&](int j, const float* q) {
            uint32_t h01, l01, h23, l23;
            hilo2(q[0], q[1], h01, l01);
            hilo2(q[2], q[3], h23, l23);
            const int off = rowoff + j * (ISPL * 2);
            *reinterpret_cast<uint2*>(sm + SM_AHI + off) = make_uint2(h01, h23);
            *reinterpret_cast<uint2*>(sm + SM_ALO + off) = make_uint2(l01, l23);
        };
        stA(0, sil);
        stA(1, t);
#pragma unroll
        for (int u = 0; u < 4; u++) { tm2[u] = t[u]; tm1[u] = 2.0f * t[u] * t[u] - 1.0f; }
        stA(2, tm1);
#pragma unroll
        for (int k = 3; k <= BASIS; k++) {
            float tk[4];
#pragma unroll
            for (int u = 0; u < 4; u++) {
                tk[u] = 2.0f * t[u] * tm1[u] - tm2[u];
                tm2[u] = tm1[u]; tm1[u] = tk[u];
            }
            stA(k, tk);
        }
    }

    // ================= build B: W2^T hi/lo, [k][o] rows =================
    // j=0 rows: plain w. 256 tasks (i, o-quad) -> 1 rep
    {
        const int iL = tid >> 4;
        const int oq = (tid & 15) * 4;
        float4 wq = *reinterpret_cast<const float4*>(&w[(size_t)(i0 + iL) * OUTF + o0 + oq]);
        uint32_t h01, l01, h23, l23;
        hilo2(wq.x, wq.y, h01, l01);
        hilo2(wq.z, wq.w, h23, l23);
        const int off = iL * BPIT + oq * 2;
        *reinterpret_cast<uint2*>(sm + SM_BHI + off) = make_uint2(h01, h23);
        *reinterpret_cast<uint2*>(sm + SM_BLO + off) = make_uint2(l01, l23);
    }
    // j=1..8 rows: c*w. 512 tasks (h, i, o-quad) -> 2 reps
#pragma unroll
    for (int r = 0; r < 2; r++) {
        const int tau = tid + r * 256;
        const int h   = tau >> 8;
        const int rem = tau & 255;
        const int iL  = rem >> 4;
        const int oq  = (rem & 15) * 4;
        float4 wq = *reinterpret_cast<const float4*>(&w[(size_t)(i0 + iL) * OUTF + o0 + oq]);
        const float* wv = &wq.x;
        float4 cq[4];
#pragma unroll
        for (int u = 0; u < 4; u++)
            cq[u] = reinterpret_cast<const float4*>(c)
                        [((size_t)(i0 + iL) * OUTF + o0 + oq + u) * 2 + h];
        const float* cf[4] = {&cq[0].x, &cq[1].x, &cq[2].x, &cq[3].x};
#pragma unroll
        for (int jj = 0; jj < 4; jj++) {
            const int j = h * 4 + jj + 1;
            float p0 = cf[0][jj] * wv[0], p1 = cf[1][jj] * wv[1];
            float p2 = cf[2][jj] * wv[2], p3 = cf[3][jj] * wv[3];
            uint32_t h01, l01, h23, l23;
            hilo2(p0, p1, h01, l01);
            hilo2(p2, p3, h23, l23);
            const int off = (j * ISPL + iL) * BPIT + oq * 2;
            *reinterpret_cast<uint2*>(sm + SM_BHI + off) = make_uint2(h01, h23);
            *reinterpret_cast<uint2*>(sm + SM_BLO + off) = make_uint2(l01, l23);
        }
    }
    __syncthreads();

    // ================= MMA mainloop: 8 warps, each 2 m-tiles x 2 n-tiles =================
    const int mgrp = wid >> 2;                   // 0..1 -> m rows mgrp*32..+31
    const int ngrp = wid & 3;                    // 0..3 -> o cols ngrp*16..+15
    const int n0   = ngrp * 16;

    const uint32_t aRow = (lane & 15), aSeg = (lane >> 4) * 16;
    const uint32_t aHiB = smem_u32(sm + SM_AHI) + (mgrp * 32 + aRow) * APIT + aSeg;
    const uint32_t aLoB = smem_u32(sm + SM_ALO) + (mgrp * 32 + aRow) * APIT + aSeg;
    const uint32_t bHiB = smem_u32(sm + SM_BHI) + (lane & 15) * BPIT + n0 * 2;
    const uint32_t bLoB = smem_u32(sm + SM_BLO) + (lane & 15) * BPIT + n0 * 2;

    float acc[2][2][4];
#pragma unroll
    for (int mt = 0; mt < 2; mt++)
#pragma unroll
        for (int nt = 0; nt < 2; nt++)
#pragma unroll
            for (int q = 0; q < 4; q++) acc[mt][nt][q] = 0.0f;

#pragma unroll
    for (int p = 0; p < 3; p++) {
        const uint32_t aB = (p < 2) ? aHiB : aLoB;     // Ah*Bh, Ah*Bl, Al*Bh
        const uint32_t bB = (p == 1) ? bLoB : bHiB;
#pragma unroll 3
        for (int s = 0; s < NK16; s++) {
            uint32_t afr[2][4];
#pragma unroll
            for (int mt = 0; mt < 2; mt++)
                ldmA(afr[mt], aB + mt * 16 * APIT + s * 32);
            uint32_t bfr[2][2];
#pragma unroll
            for (int nt = 0; nt < 2; nt++)
                ldmB(bfr[nt], bB + s * 16 * BPIT + nt * 16);
#pragma unroll
            for (int mt = 0; mt < 2; mt++)
#pragma unroll
                for (int nt = 0; nt < 2; nt++)
                    mma16816(acc[mt][nt], afr[mt], bfr[nt]);
        }
    }

    // ================= write partials =================
    float* pp = g_partial + (size_t)ks * (BATCH * OUTF);
#pragma unroll
    for (int mt = 0; mt < 2; mt++)
#pragma unroll
        for (int nt = 0; nt < 2; nt++) {
            const int row = mgrp * 32 + mt * 16 + (lane >> 2);
            const int col = o0 + n0 + nt * 8 + (lane & 3) * 2;
            *reinterpret_cast<float2*>(pp + (size_t)row * OUTF + col) =
                make_float2(acc[mt][nt][0], acc[mt][nt][1]);
            *reinterpret_cast<float2*>(pp + (size_t)(row + 8) * OUTF + col) =
                make_float2(acc[mt][nt][2], acc[mt][nt][3]);
        }

    // ================= fused reduce: last CTA per o-column =================
    __threadfence();
    if (tid == 0)
        s_last = (atomicAdd(&g_ctr[blockIdx.x], 1) == NSPLIT - 1) ? 1 : 0;
    __syncthreads();
    if (s_last) {
        __threadfence();
        // 64 b x 64 o = 1024 float4; 256 threads -> 4 each
#pragma unroll
        for (int rep = 0; rep < 4; rep++) {
            const int qi = tid + rep * 256;
            const int b  = qi >> 4;
            const int oq = qi & 15;
            const float* base = g_partial + (size_t)b * OUTF + o0 + oq * 4;
            float4 s = make_float4(0.f, 0.f, 0.f, 0.f);
#pragma unroll
            for (int sp = 0; sp < NSPLIT; sp++) {
                float4 v = *reinterpret_cast<const float4*>(base + (size_t)sp * (BATCH * OUTF));
                s.x += v.x; s.y += v.y; s.z += v.z; s.w += v.w;
            }
            *reinterpret_cast<float4*>(out + (size_t)b * OUTF + o0 + oq * 4) = s;
        }
        __syncthreads();
        if (tid == 0) g_ctr[blockIdx.x] = 0;           // reset for graph replay
    }
}

extern "C" void kernel_launch(void* const* d_in, const int* in_sizes, int n_in,
                              void* d_out, int out_size) {
    const float* x = (const float*)d_in[0];
    const float* w = (const float*)d_in[1];
    const float* c = (const float*)d_in[2];
    float* out = (float*)d_out;

    cudaFuncSetAttribute(kan_mma, cudaFuncAttributeMaxDynamicSharedMemorySize, SM_TOT);
    kan_mma<<<dim3(NCOL, NSPLIT), 256, SM_TOT>>>(x, w, c, out);
}

// round 17
// speedup vs baseline: 1.1047x; 1.1047x over previous
#include <cuda_runtime.h>
#include <cuda_bf16.h>
#include <cstdint>

// LinearKAN via warp-level bf16 mma.sync (m16n8k16) with hi/lo compensation.
//   out[b,o] = sum_{j,i} basis_j(x[b,i]) * W2[(j,i),o]
//   basis_0 = silu(x), basis_j = T_j(clip(tanh(x)));  W2[(j,i),o] = j==0 ? w[i,o] : c[i,o,j-1]*w[i,o]
// Grid (8 o-tiles x 16 i-splits) x 512 threads (16 warps), 1 CTA/SM.
// A,B stored as bf16 hi+lo; D = Ah*Bh + Ah*Bl + Al*Bh in f32 accum (drop lo*lo).
// Fast-math basis build (expf-based tanh, no libm tanhf/FDIV slow paths).

#define BATCH 64
#define INF   512
#define OUTF  512
#define BASIS 8

#define NSPLIT 16
#define ISPL   (INF / NSPLIT)      // 32 i's per CTA
#define NO     64                  // o's per CTA
#define NCOL   (OUTF / NO)         // 8
#define KB     (9 * ISPL)          // 288 k per CTA
#define NK16   (KB / 16)           // 18 k16 steps per pass

// smem pitches (bytes): 16B-aligned, conflict-free ldmatrix phases
#define APIT 592                   // A row pitch (576B data + 16 pad)
#define BPIT 144                   // B row pitch (128B data + 16 pad)

#define SM_AHI 0
#define SM_ALO (SM_AHI + 64 * APIT)        // 37888
#define SM_BHI (SM_ALO + 64 * APIT)        // 75776
#define SM_BLO (SM_BHI + KB * BPIT)        // 117248
#define SM_TOT (SM_BLO + KB * BPIT)        // 158720

__device__ float g_partial[NSPLIT * BATCH * OUTF];   // 2 MB
__device__ int   g_ctr[NCOL];                        // zero-init; self-resetting

// ---------------- helpers ----------------
__device__ __forceinline__ uint32_t smem_u32(const void* p) {
    uint32_t a;
    asm("{ .reg .u64 t; cvta.to.shared.u64 t, %1; cvt.u32.u64 %0, t; }" : "=r"(a) : "l"(p));
    return a;
}
__device__ __forceinline__ void hilo2(float v0, float v1, uint32_t& hi, uint32_t& lo) {
    asm("cvt.rn.bf16x2.f32 %0, %1, %2;" : "=r"(hi) : "f"(v1), "f"(v0));  // low16 = v0
    float h0 = __uint_as_float(hi << 16);
    float h1 = __uint_as_float(hi & 0xffff0000u);
    float l0 = v0 - h0, l1 = v1 - h1;
    asm("cvt.rn.bf16x2.f32 %0, %1, %2;" : "=r"(lo) : "f"(l1), "f"(l0));
}
// overflow-safe fast tanh: e = exp(-2|x|) in (0,1], t = sign(x)*(1-e)/(1+e)
__device__ __forceinline__ float fast_tanh(float x) {
    float e = __expf(-2.0f * fabsf(x));
    float t = __fdividef(1.0f - e, 1.0f + e);
    return copysignf(t, x);
}
__device__ __forceinline__ void ldmA(uint32_t* a, uint32_t addr) {
    asm volatile("ldmatrix.sync.aligned.m8n8.x4.shared.b16 {%0,%1,%2,%3}, [%4];"
                 : "=r"(a[0]), "=r"(a[1]), "=r"(a[2]), "=r"(a[3]) : "r"(addr));
}
__device__ __forceinline__ void ldmB(uint32_t* b, uint32_t addr) {
    asm volatile("ldmatrix.sync.aligned.m8n8.x2.trans.shared.b16 {%0,%1}, [%2];"
                 : "=r"(b[0]), "=r"(b[1]) : "r"(addr));
}
__device__ __forceinline__ void mma16816(float* d, const uint32_t* a, const uint32_t* b) {
    asm volatile("mma.sync.aligned.m16n8k16.row.col.f32.bf16.bf16.f32 "
                 "{%0,%1,%2,%3}, {%4,%5,%6,%7}, {%8,%9}, {%0,%1,%2,%3};"
                 : "+f"(d[0]), "+f"(d[1]), "+f"(d[2]), "+f"(d[3])
                 : "r"(a[0]), "r"(a[1]), "r"(a[2]), "r"(a[3]), "r"(b[0]), "r"(b[1]));
}

__global__ __launch_bounds__(512, 1)
void kan_mma(const float* __restrict__ x,
             const float* __restrict__ w,
             const float* __restrict__ c,
             float* __restrict__ out) {
    extern __shared__ char sm[];
    __shared__ int s_last;

    const int tid  = threadIdx.x;
    const int wid  = tid >> 5, lane = tid & 31;
    const int o0   = blockIdx.x * NO;
    const int ks   = blockIdx.y;
    const int i0   = ks * ISPL;

    // ================= build A: basis hi/lo, [b][k] rows, k = j*32 + i =================
    // 512 tasks (b, i-quad) -> exactly 1 rep
    {
        const int b  = tid >> 3;
        const int iq = (tid & 7) * 4;
        float4 xv = *reinterpret_cast<const float4*>(&x[(size_t)b * INF + i0 + iq]);
        float v[4] = {xv.x, xv.y, xv.z, xv.w};
        float sil[4], t[4], tm1[4], tm2[4];
#pragma unroll
        for (int u = 0; u < 4; u++) {
            sil[u] = v[u] * __fdividef(1.0f, 1.0f + __expf(-v[u]));
            float tt = fast_tanh(v[u]);
            t[u] = fminf(fmaxf(tt, -1.0f + 1e-6f), 1.0f - 1e-6f);
        }
        const int rowoff = b * APIT + iq * 2;
        auto stA = [&](int j, const float* q) {
            uint32_t h01, l01, h23, l23;
            hilo2(q[0], q[1], h01, l01);
            hilo2(q[2], q[3], h23, l23);
            const int off = rowoff + j * (ISPL * 2);
            *reinterpret_cast<uint2*>(sm + SM_AHI + off) = make_uint2(h01, h23);
            *reinterpret_cast<uint2*>(sm + SM_ALO + off) = make_uint2(l01, l23);
        };
        stA(0, sil);
        stA(1, t);
#pragma unroll
        for (int u = 0; u < 4; u++) { tm2[u] = t[u]; tm1[u] = 2.0f * t[u] * t[u] - 1.0f; }
        stA(2, tm1);
#pragma unroll
        for (int k = 3; k <= BASIS; k++) {
            float tk[4];
#pragma unroll
            for (int u = 0; u < 4; u++) {
                tk[u] = 2.0f * t[u] * tm1[u] - tm2[u];
                tm2[u] = tm1[u]; tm1[u] = tk[u];
            }
            stA(k, tk);
        }
    }

    // ================= build B: W2^T hi/lo, [k][o] rows =================
    // j=0 rows: plain w. 512 tasks (i, o-quad) -> 1 rep
    {
        const int iL = tid >> 4;
        const int oq = (tid & 15) * 4;
        float4 wq = *reinterpret_cast<const float4*>(&w[(size_t)(i0 + iL) * OUTF + o0 + oq]);
        uint32_t h01, l01, h23, l23;
        hilo2(wq.x, wq.y, h01, l01);
        hilo2(wq.z, wq.w, h23, l23);
        const int off = iL * BPIT + oq * 2;
        *reinterpret_cast<uint2*>(sm + SM_BHI + off) = make_uint2(h01, h23);
        *reinterpret_cast<uint2*>(sm + SM_BLO + off) = make_uint2(l01, l23);
    }
    // j=1..8 rows: c*w. 512 tasks (i, o-quad), each loads FULL 32B c per o (all 8 j's)
    {
        const int iL = tid >> 4;
        const int oq = (tid & 15) * 4;
        float4 wq = *reinterpret_cast<const float4*>(&w[(size_t)(i0 + iL) * OUTF + o0 + oq]);
        const float* wv = &wq.x;
        float4 cq[4][2];                                   // [o within quad][j-half]
#pragma unroll
        for (int u = 0; u < 4; u++) {
            const float4* cp = reinterpret_cast<const float4*>(c) +
                               ((size_t)(i0 + iL) * OUTF + o0 + oq + u) * 2;
            cq[u][0] = cp[0];
            cq[u][1] = cp[1];
        }
#pragma unroll
        for (int h = 0; h < 2; h++) {
            const float* cf[4] = {&cq[0][h].x, &cq[1][h].x, &cq[2][h].x, &cq[3][h].x};
#pragma unroll
            for (int jj = 0; jj < 4; jj++) {
                const int j = h * 4 + jj + 1;
                float p0 = cf[0][jj] * wv[0], p1 = cf[1][jj] * wv[1];
                float p2 = cf[2][jj] * wv[2], p3 = cf[3][jj] * wv[3];
                uint32_t h01, l01, h23, l23;
                hilo2(p0, p1, h01, l01);
                hilo2(p2, p3, h23, l23);
                const int off = (j * ISPL + iL) * BPIT + oq * 2;
                *reinterpret_cast<uint2*>(sm + SM_BHI + off) = make_uint2(h01, h23);
                *reinterpret_cast<uint2*>(sm + SM_BLO + off) = make_uint2(l01, l23);
            }
        }
    }
    __syncthreads();

    // ================= MMA mainloop: 16 warps, each 1 m-tile x 2 n-tiles =================
    const int mgrp = wid >> 2;                   // 0..3 -> m rows mgrp*16..+15
    const int ngrp = wid & 3;                    // 0..3 -> o cols ngrp*16..+15
    const int n0   = ngrp * 16;

    const uint32_t aRow = (lane & 15), aSeg = (lane >> 4) * 16;
    const uint32_t aHiB = smem_u32(sm + SM_AHI) + (mgrp * 16 + aRow) * APIT + aSeg;
    const uint32_t aLoB = smem_u32(sm + SM_ALO) + (mgrp * 16 + aRow) * APIT + aSeg;
    const uint32_t bHiB = smem_u32(sm + SM_BHI) + (lane & 15) * BPIT + n0 * 2;
    const uint32_t bLoB = smem_u32(sm + SM_BLO) + (lane & 15) * BPIT + n0 * 2;

    float acc[2][4];
#pragma unroll
    for (int nt = 0; nt < 2; nt++)
#pragma unroll
        for (int q = 0; q < 4; q++) acc[nt][q] = 0.0f;

#pragma unroll
    for (int p = 0; p < 3; p++) {
        const uint32_t aB = (p < 2) ? aHiB : aLoB;     // Ah*Bh, Ah*Bl, Al*Bh
        const uint32_t bB = (p == 1) ? bLoB : bHiB;
#pragma unroll 6
        for (int s = 0; s < NK16; s++) {
            uint32_t afr[4];
            ldmA(afr, aB + s * 32);
            uint32_t bfr[2][2];
#pragma unroll
            for (int nt = 0; nt < 2; nt++)
                ldmB(bfr[nt], bB + s * 16 * BPIT + nt * 16);
#pragma unroll
            for (int nt = 0; nt < 2; nt++)
                mma16816(acc[nt], afr, bfr[nt]);
        }
    }

    // ================= write partials =================
    float* pp = g_partial + (size_t)ks * (BATCH * OUTF);
#pragma unroll
    for (int nt = 0; nt < 2; nt++) {
        const int row = mgrp * 16 + (lane >> 2);
        const int col = o0 + n0 + nt * 8 + (lane & 3) * 2;
        *reinterpret_cast<float2*>(pp + (size_t)row * OUTF + col) =
            make_float2(acc[nt][0], acc[nt][1]);
        *reinterpret_cast<float2*>(pp + (size_t)(row + 8) * OUTF + col) =
            make_float2(acc[nt][2], acc[nt][3]);
    }

    // ================= fused reduce: last CTA per o-column =================
    __threadfence();
    if (tid == 0)
        s_last = (atomicAdd(&g_ctr[blockIdx.x], 1) == NSPLIT - 1) ? 1 : 0;
    __syncthreads();
    if (s_last) {
        __threadfence();
        // 64 b x 64 o = 1024 float4; 512 threads -> 2 each
#pragma unroll
        for (int rep = 0; rep < 2; rep++) {
            const int qi = tid + rep * 512;
            const int b  = qi >> 4;
            const int oq = qi & 15;
            const float* base = g_partial + (size_t)b * OUTF + o0 + oq * 4;
            float4 s = make_float4(0.f, 0.f, 0.f, 0.f);
#pragma unroll
            for (int sp = 0; sp < NSPLIT; sp++) {
                float4 v = *reinterpret_cast<const float4*>(base + (size_t)sp * (BATCH * OUTF));
                s.x += v.x; s.y += v.y; s.z += v.z; s.w += v.w;
            }
            *reinterpret_cast<float4*>(out + (size_t)b * OUTF + o0 + oq * 4) = s;
        }
        __syncthreads();
        if (tid == 0) g_ctr[blockIdx.x] = 0;           // reset for graph replay
    }
}

extern "C" void kernel_launch(void* const* d_in, const int* in_sizes, int n_in,
                              void* d_out, int out_size) {
    const float* x = (const float*)d_in[0];
    const float* w = (const float*)d_in[1];
    const float* c = (const float*)d_in[2];
    float* out = (float*)d_out;

    cudaFuncSetAttribute(kan_mma, cudaFuncAttributeMaxDynamicSharedMemorySize, SM_TOT);
    kan_mma<<<dim3(NCOL, NSPLIT), 512, SM_TOT>>>(x, w, c, out);
}